// round 12
// baseline (speedup 1.0000x reference)
#include <cuda_runtime.h>
#include <cuda_bf16.h>

// ConsistencyLoss: KL(softmax(soft/T) || softmax(logits/T)) * T^2, batchmean.
// B = 4.19M, C = 5, T = 3.
// Warp-tile SMEM staging + software pipelining (register prefetch of next tile
// overlaps its DRAM latency with compute of the current tile).

#define NUM_CLASSES 5
#define TEMP 3.0f
#define INV_T (1.0f / 3.0f)
#define L2E_T 0.4808983469629878f   // log2(e)/3
#define LN2   0.6931471805599453f
#define MAX_BLOCKS 8192
#define GRID_BLOCKS 912

__device__ float g_partials[MAX_BLOCKS];
__device__ unsigned int g_count;    // zero at load; reset by last block each run

__device__ __forceinline__ float ex2(float x) {
    float r; asm("ex2.approx.ftz.f32 %0, %1;" : "=f"(r) : "f"(x)); return r;
}
__device__ __forceinline__ float lg2(float x) {
    float r; asm("lg2.approx.ftz.f32 %0, %1;" : "=f"(r) : "f"(x)); return r;
}

// Core KL for one sample; logits come from SMEM (5 floats + 2 indexed reads).
__device__ __forceinline__ float kl_sample_smem(float s, const float* __restrict__ l) {
    float sc   = s * 5.0f;
    float fidx = floorf(sc);
    int   idx  = (int)fidx;                 // s in [0,1] -> idx in [0,4]
    float d0   = sc - fidx - 0.5f;          // signed dist to bin center, *5
    float dist = fabsf(d0);

    int  nbi   = idx + ((d0 > 0.0f) ? 1 : -1);
    bool valid = ((unsigned)nbi <= 4u);
    float a = valid ? (1.0f - dist) : 1.0f;
    float b = valid ? dist : 0.0f;
    nbi = valid ? nbi : idx;

    float l0 = l[0], l1 = l[1], l2 = l[2], l3 = l[3], l4 = l[4];
    float lidx = l[idx];
    float lnb  = l[nbi];

    float e_m  = ex2(a * L2E_T);
    float e_nb = ex2(b * L2E_T);
    float Zp   = e_m + e_nb + 3.0f;
    float Sps  = e_m * a + e_nb * b;        // Zp * sum(p * soft)

    float Zq = ex2(l0 * L2E_T) + ex2(l1 * L2E_T) + ex2(l2 * L2E_T)
             + ex2(l3 * L2E_T) + ex2(l4 * L2E_T);
    float suml = (l0 + l1) + (l2 + l3) + l4;
    float wl   = suml + (e_m - 1.0f) * lidx + (e_nb - 1.0f) * lnb;  // Zp * sum(p*l)

    float rZp = __fdividef(1.0f, Zp);
    // kl_i = (Sps - wl)/(Zp*T) + log(Zq/Zp)
    return (Sps - wl) * rZp * INV_T + lg2(Zq * rZp) * LN2;
}

__device__ __forceinline__ float sel5(float l0, float l1, float l2, float l3, float l4, int i) {
    float r = l0;
    r = (i == 1) ? l1 : r;
    r = (i == 2) ? l2 : r;
    r = (i == 3) ? l3 : r;
    r = (i == 4) ? l4 : r;
    return r;
}

// Register-path variant for the scalar tail.
__device__ __forceinline__ float kl_sample_reg(float s, float l0, float l1,
                                               float l2, float l3, float l4) {
    float sc   = s * 5.0f;
    float fidx = floorf(sc);
    int   idx  = (int)fidx;
    float d0   = sc - fidx - 0.5f;
    float dist = fabsf(d0);

    int  nbi   = idx + ((d0 > 0.0f) ? 1 : -1);
    bool valid = ((unsigned)nbi <= 4u);
    float a = valid ? (1.0f - dist) : 1.0f;
    float b = valid ? dist : 0.0f;
    nbi = valid ? nbi : idx;

    float lidx = sel5(l0, l1, l2, l3, l4, idx);
    float lnb  = sel5(l0, l1, l2, l3, l4, nbi);

    float e_m  = ex2(a * L2E_T);
    float e_nb = ex2(b * L2E_T);
    float Zp   = e_m + e_nb + 3.0f;
    float Sps  = e_m * a + e_nb * b;

    float Zq = ex2(l0 * L2E_T) + ex2(l1 * L2E_T) + ex2(l2 * L2E_T)
             + ex2(l3 * L2E_T) + ex2(l4 * L2E_T);
    float suml = (l0 + l1) + (l2 + l3) + l4;
    float wl   = suml + (e_m - 1.0f) * lidx + (e_nb - 1.0f) * lnb;

    float rZp = __fdividef(1.0f, Zp);
    return (Sps - wl) * rZp * INV_T + lg2(Zq * rZp) * LN2;
}

__global__ void __launch_bounds__(256)
cl_fused_kernel(const float* __restrict__ qs, const float* __restrict__ lg,
                float* __restrict__ out, int n) {
    __shared__ float4 sdata4[8 * 160];      // 160 float4 (2560B) per warp
    __shared__ float warp_sums[8];
    __shared__ int   s_is_last;

    int lane = threadIdx.x & 31;
    int wid  = threadIdx.x >> 5;
    float4*      swv = sdata4 + wid * 160;
    const float* swf = (const float*)swv;

    int warp_g = blockIdx.x * 8 + wid;
    int nwarps = gridDim.x * 8;
    int ntiles = n >> 7;                    // 128 samples per warp tile

    const float4* lg4 = (const float4*)lg;

    float acc = 0.0f;

    int t = warp_g;
    if (t < ntiles) {
        // ---- prologue: prefetch first tile into registers ----
        const float4* src = lg4 + (size_t)t * 160;
        float4 v0 = src[lane];
        float4 v1 = src[lane + 32];
        float4 v2 = src[lane + 64];
        float4 v3 = src[lane + 96];
        float4 v4 = src[lane + 128];
        int sb = t << 7;
        float s0 = qs[sb + lane];
        float s1 = qs[sb + lane + 32];
        float s2 = qs[sb + lane + 64];
        float s3 = qs[sb + lane + 96];

        for (;;) {
            // stage current tile into SMEM
            swv[lane]       = v0;
            swv[lane + 32]  = v1;
            swv[lane + 64]  = v2;
            swv[lane + 96]  = v3;
            swv[lane + 128] = v4;
            float cs0 = s0, cs1 = s1, cs2 = s2, cs3 = s3;
            __syncwarp();

            // issue next tile's loads NOW (in flight during compute below)
            int tn = t + nwarps;
            bool more = (tn < ntiles);
            int tsafe = more ? tn : t;       // stay in-bounds; values unused if !more
            const float4* nsrc = lg4 + (size_t)tsafe * 160;
            v0 = nsrc[lane];
            v1 = nsrc[lane + 32];
            v2 = nsrc[lane + 64];
            v3 = nsrc[lane + 96];
            v4 = nsrc[lane + 128];
            int nsb = tsafe << 7;
            s0 = qs[nsb + lane];
            s1 = qs[nsb + lane + 32];
            s2 = qs[nsb + lane + 64];
            s3 = qs[nsb + lane + 96];

            // compute current tile from SMEM (lane i: samples i, i+32, i+64, i+96;
            // float index 5*sample + c -> bank (5*lane + c) mod 32, conflict-free)
            acc += kl_sample_smem(cs0, swf + lane * 5);
            acc += kl_sample_smem(cs1, swf + (lane + 32) * 5);
            acc += kl_sample_smem(cs2, swf + (lane + 64) * 5);
            acc += kl_sample_smem(cs3, swf + (lane + 96) * 5);
            __syncwarp();

            if (!more) break;
            t = tn;
        }
    }

    // Scalar tail (n % 128 samples), direct global loads.
    int rem_base = ntiles << 7;
    int gid = blockIdx.x * blockDim.x + threadIdx.x;
    if (gid < (n - rem_base)) {
        int i = rem_base + gid;
        const float* l = lg + (size_t)i * NUM_CLASSES;
        acc += kl_sample_reg(qs[i], l[0], l[1], l[2], l[3], l[4]);
    }

    // ---- intra-block reduction ----
    #pragma unroll
    for (int off = 16; off > 0; off >>= 1)
        acc += __shfl_xor_sync(0xFFFFFFFF, acc, off);

    if (lane == 0) warp_sums[wid] = acc;
    __syncthreads();

    if (threadIdx.x == 0) {
        float bs = 0.0f;
        #pragma unroll
        for (int w = 0; w < 8; w++) bs += warp_sums[w];
        g_partials[blockIdx.x] = bs;
        __threadfence();
        unsigned int old = atomicAdd(&g_count, 1u);
        s_is_last = (old == gridDim.x - 1) ? 1 : 0;
    }
    __syncthreads();

    // ---- last block finalizes (deterministic order) ----
    if (s_is_last) {
        __threadfence();
        float fs = 0.0f;
        for (int i = threadIdx.x; i < gridDim.x; i += blockDim.x)
            fs += __ldcg(&g_partials[i]);

        #pragma unroll
        for (int off = 16; off > 0; off >>= 1)
            fs += __shfl_xor_sync(0xFFFFFFFF, fs, off);
        if (lane == 0) warp_sums[wid] = fs;
        __syncthreads();

        if (threadIdx.x == 0) {
            double total = 0.0;
            #pragma unroll
            for (int w = 0; w < 8; w++) total += (double)warp_sums[w];
            out[0] = (float)(total / (double)n * (double)(TEMP * TEMP));
            g_count = 0;    // reset for next graph replay
        }
    }
}

extern "C" void kernel_launch(void* const* d_in, const int* in_sizes, int n_in,
                              void* d_out, int out_size) {
    const float* qs = (const float*)d_in[0];   // quality_score [B]
    const float* lg = (const float*)d_in[1];   // class_logits  [B, 5]
    float* out = (float*)d_out;
    int n = in_sizes[0];

    int blocks = GRID_BLOCKS;
    int ntiles = n >> 7;
    if (ntiles < 1) ntiles = 1;
    if (blocks * 8 > ntiles) blocks = (ntiles + 7) / 8;   // small-n safety
    if (blocks < 1) blocks = 1;
    if (blocks > MAX_BLOCKS) blocks = MAX_BLOCKS;

    cl_fused_kernel<<<blocks, 256>>>(qs, lg, out, n);
}

// round 14
// speedup vs baseline: 1.0955x; 1.0955x over previous
#include <cuda_runtime.h>
#include <cuda_bf16.h>
#include <cstdint>

// ConsistencyLoss: KL(softmax(soft/T) || softmax(logits/T)) * T^2, batchmean.
// B = 4.19M, C = 5, T = 3.
// cp.async (LDGSTS) double-buffered warp tiles: tile t+stride streams
// GMEM->SMEM while tile t computes. ptxas cannot de-pipeline LDGSTS.

#define NUM_CLASSES 5
#define TEMP 3.0f
#define INV_T (1.0f / 3.0f)
#define L2E_T 0.4808983469629878f   // log2(e)/3
#define LN2   0.6931471805599453f
#define MAX_BLOCKS 8192
#define GRID_BLOCKS 760             // 152 SMs * 5 resident (40KB smem/block)

__device__ float g_partials[MAX_BLOCKS];
__device__ unsigned int g_count;    // zero at load; reset by last block each run

__device__ __forceinline__ float ex2(float x) {
    float r; asm("ex2.approx.ftz.f32 %0, %1;" : "=f"(r) : "f"(x)); return r;
}
__device__ __forceinline__ float lg2(float x) {
    float r; asm("lg2.approx.ftz.f32 %0, %1;" : "=f"(r) : "f"(x)); return r;
}

#define CP_ASYNC16(sa, ga) \
    asm volatile("cp.async.cg.shared.global [%0], [%1], 16;" :: "r"(sa), "l"(ga))
#define CP_COMMIT() asm volatile("cp.async.commit_group;" ::: "memory")

// Core KL for one sample; logits come from SMEM (5 floats + 2 indexed reads).
__device__ __forceinline__ float kl_sample_smem(float s, const float* __restrict__ l) {
    float sc   = s * 5.0f;
    float fidx = floorf(sc);
    int   idx  = (int)fidx;                 // s in [0,1] -> idx in [0,4]
    float d0   = sc - fidx - 0.5f;          // signed dist to bin center, *5
    float dist = fabsf(d0);

    int  nbi   = idx + ((d0 > 0.0f) ? 1 : -1);
    bool valid = ((unsigned)nbi <= 4u);
    float a = valid ? (1.0f - dist) : 1.0f;
    float b = valid ? dist : 0.0f;
    nbi = valid ? nbi : idx;

    float l0 = l[0], l1 = l[1], l2 = l[2], l3 = l[3], l4 = l[4];
    float lidx = l[idx];
    float lnb  = l[nbi];

    float e_m  = ex2(a * L2E_T);
    float e_nb = ex2(b * L2E_T);
    float Zp   = e_m + e_nb + 3.0f;
    float Sps  = e_m * a + e_nb * b;        // Zp * sum(p * soft)

    float Zq = ex2(l0 * L2E_T) + ex2(l1 * L2E_T) + ex2(l2 * L2E_T)
             + ex2(l3 * L2E_T) + ex2(l4 * L2E_T);
    float suml = (l0 + l1) + (l2 + l3) + l4;
    float wl   = suml + (e_m - 1.0f) * lidx + (e_nb - 1.0f) * lnb;  // Zp * sum(p*l)

    float rZp = __fdividef(1.0f, Zp);
    // kl_i = (Sps - wl)/(Zp*T) + log(Zq/Zp)
    return (Sps - wl) * rZp * INV_T + lg2(Zq * rZp) * LN2;
}

__device__ __forceinline__ float sel5(float l0, float l1, float l2, float l3, float l4, int i) {
    float r = l0;
    r = (i == 1) ? l1 : r;
    r = (i == 2) ? l2 : r;
    r = (i == 3) ? l3 : r;
    r = (i == 4) ? l4 : r;
    return r;
}

// Register-path variant for the scalar tail.
__device__ __forceinline__ float kl_sample_reg(float s, float l0, float l1,
                                               float l2, float l3, float l4) {
    float sc   = s * 5.0f;
    float fidx = floorf(sc);
    int   idx  = (int)fidx;
    float d0   = sc - fidx - 0.5f;
    float dist = fabsf(d0);

    int  nbi   = idx + ((d0 > 0.0f) ? 1 : -1);
    bool valid = ((unsigned)nbi <= 4u);
    float a = valid ? (1.0f - dist) : 1.0f;
    float b = valid ? dist : 0.0f;
    nbi = valid ? nbi : idx;

    float lidx = sel5(l0, l1, l2, l3, l4, idx);
    float lnb  = sel5(l0, l1, l2, l3, l4, nbi);

    float e_m  = ex2(a * L2E_T);
    float e_nb = ex2(b * L2E_T);
    float Zp   = e_m + e_nb + 3.0f;
    float Sps  = e_m * a + e_nb * b;

    float Zq = ex2(l0 * L2E_T) + ex2(l1 * L2E_T) + ex2(l2 * L2E_T)
             + ex2(l3 * L2E_T) + ex2(l4 * L2E_T);
    float suml = (l0 + l1) + (l2 + l3) + l4;
    float wl   = suml + (e_m - 1.0f) * lidx + (e_nb - 1.0f) * lnb;

    float rZp = __fdividef(1.0f, Zp);
    return (Sps - wl) * rZp * INV_T + lg2(Zq * rZp) * LN2;
}

__global__ void __launch_bounds__(256)
cl_fused_kernel(const float* __restrict__ qs, const float* __restrict__ lg,
                float* __restrict__ out, int n) {
    // Per warp: 2 buffers x 160 float4 (2560B each) = 5120B; 8 warps = 40KB.
    __shared__ float4 sdata4[8 * 320];
    __shared__ float warp_sums[8];
    __shared__ int   s_is_last;

    int lane = threadIdx.x & 31;
    int wid  = threadIdx.x >> 5;
    float4* wslice = sdata4 + wid * 320;
    unsigned int sbase = (unsigned int)__cvta_generic_to_shared(wslice)
                       + (unsigned int)lane * 16u;

    int warp_g = blockIdx.x * 8 + wid;
    int nwarps = gridDim.x * 8;
    int ntiles = n >> 7;                    // 128 samples per warp tile

    const float4* lg4 = (const float4*)lg;

    float acc = 0.0f;

    int t = warp_g;
    if (t < ntiles) {
        // ---- prologue: async-stage first tile into buffer 0 ----
        {
            const float4* g = lg4 + (size_t)t * 160 + lane;
            CP_ASYNC16(sbase,          g);
            CP_ASYNC16(sbase + 512u,   g + 32);
            CP_ASYNC16(sbase + 1024u,  g + 64);
            CP_ASYNC16(sbase + 1536u,  g + 96);
            CP_ASYNC16(sbase + 2048u,  g + 128);
            CP_COMMIT();
        }
        int sb = t << 7;
        float s0 = qs[sb + lane];
        float s1 = qs[sb + lane + 32];
        float s2 = qs[sb + lane + 64];
        float s3 = qs[sb + lane + 96];

        int b = 0;
        for (;;) {
            int tn = t + nwarps;
            bool more = (tn < ntiles);
            float ns0 = 0.f, ns1 = 0.f, ns2 = 0.f, ns3 = 0.f;
            if (more) {
                // stream next tile into the other buffer (overlaps compute below)
                const float4* g = lg4 + (size_t)tn * 160 + lane;
                unsigned int sd = sbase + (unsigned int)(b ^ 1) * 2560u;
                CP_ASYNC16(sd,          g);
                CP_ASYNC16(sd + 512u,   g + 32);
                CP_ASYNC16(sd + 1024u,  g + 64);
                CP_ASYNC16(sd + 1536u,  g + 96);
                CP_ASYNC16(sd + 2048u,  g + 128);
                CP_COMMIT();
                int nsb = tn << 7;
                ns0 = qs[nsb + lane];
                ns1 = qs[nsb + lane + 32];
                ns2 = qs[nsb + lane + 64];
                ns3 = qs[nsb + lane + 96];
            }

            // wait for current buffer's copies (per-lane), then warp-sync so
            // every lane's copies are complete before cross-lane SMEM reads.
            if (more) { asm volatile("cp.async.wait_group 1;" ::: "memory"); }
            else      { asm volatile("cp.async.wait_group 0;" ::: "memory"); }
            __syncwarp();

            // compute current tile: lane i -> samples i, i+32, i+64, i+96;
            // float index 5*sample + c -> bank (5*lane + c) mod 32, conflict-free.
            const float* swf = (const float*)(wslice + b * 160);
            acc += kl_sample_smem(s0, swf + lane * 5);
            acc += kl_sample_smem(s1, swf + (lane + 32) * 5);
            acc += kl_sample_smem(s2, swf + (lane + 64) * 5);
            acc += kl_sample_smem(s3, swf + (lane + 96) * 5);
            __syncwarp();                   // reads done before buffer reuse

            if (!more) break;
            s0 = ns0; s1 = ns1; s2 = ns2; s3 = ns3;
            b ^= 1;
            t = tn;
        }
    }

    // Scalar tail (n % 128 samples), direct global loads.
    int rem_base = ntiles << 7;
    int gid = blockIdx.x * blockDim.x + threadIdx.x;
    if (gid < (n - rem_base)) {
        int i = rem_base + gid;
        const float* l = lg + (size_t)i * NUM_CLASSES;
        acc += kl_sample_reg(qs[i], l[0], l[1], l[2], l[3], l[4]);
    }

    // ---- intra-block reduction ----
    #pragma unroll
    for (int off = 16; off > 0; off >>= 1)
        acc += __shfl_xor_sync(0xFFFFFFFF, acc, off);

    if (lane == 0) warp_sums[wid] = acc;
    __syncthreads();

    if (threadIdx.x == 0) {
        float bs = 0.0f;
        #pragma unroll
        for (int w = 0; w < 8; w++) bs += warp_sums[w];
        g_partials[blockIdx.x] = bs;
        __threadfence();
        unsigned int old = atomicAdd(&g_count, 1u);
        s_is_last = (old == gridDim.x - 1) ? 1 : 0;
    }
    __syncthreads();

    // ---- last block finalizes (deterministic order) ----
    if (s_is_last) {
        __threadfence();
        float fs = 0.0f;
        for (int i = threadIdx.x; i < gridDim.x; i += blockDim.x)
            fs += __ldcg(&g_partials[i]);

        #pragma unroll
        for (int off = 16; off > 0; off >>= 1)
            fs += __shfl_xor_sync(0xFFFFFFFF, fs, off);
        if (lane == 0) warp_sums[wid] = fs;
        __syncthreads();

        if (threadIdx.x == 0) {
            double total = 0.0;
            #pragma unroll
            for (int w = 0; w < 8; w++) total += (double)warp_sums[w];
            out[0] = (float)(total / (double)n * (double)(TEMP * TEMP));
            g_count = 0;    // reset for next graph replay
        }
    }
}

extern "C" void kernel_launch(void* const* d_in, const int* in_sizes, int n_in,
                              void* d_out, int out_size) {
    const float* qs = (const float*)d_in[0];   // quality_score [B]
    const float* lg = (const float*)d_in[1];   // class_logits  [B, 5]
    float* out = (float*)d_out;
    int n = in_sizes[0];

    int blocks = GRID_BLOCKS;
    int ntiles = n >> 7;
    if (ntiles < 1) ntiles = 1;
    if (blocks * 8 > ntiles) blocks = (ntiles + 7) / 8;   // small-n safety
    if (blocks < 1) blocks = 1;
    if (blocks > MAX_BLOCKS) blocks = MAX_BLOCKS;

    cl_fused_kernel<<<blocks, 256>>>(qs, lg, out, n);
}

// round 16
// speedup vs baseline: 1.1824x; 1.0794x over previous
#include <cuda_runtime.h>
#include <cuda_bf16.h>
#include <cstdint>

// ConsistencyLoss: KL(softmax(soft/T) || softmax(logits/T)) * T^2, batchmean.
// B = 4.19M, C = 5, T = 3.
// cp.async double-buffered warp tiles + clamp-form soft target:
// soft = lerp between bins j and j+1 with u = clamp(5s-0.5,0,4), j=min((int)u,3),
// f = u-j. Equivalent to the reference's branchy construction, far fewer instrs.

#define NUM_CLASSES 5
#define TEMP 3.0f
#define INV_T (1.0f / 3.0f)
#define L2E_T 0.4808983469629878f   // log2(e)/3
#define LN2   0.6931471805599453f
#define MAX_BLOCKS 8192
#define GRID_BLOCKS 760             // 152 SMs * 5 resident (40KB smem/block)

__device__ float g_partials[MAX_BLOCKS];
__device__ unsigned int g_count;    // zero at load; reset by last block each run

__device__ __forceinline__ float ex2(float x) {
    float r; asm("ex2.approx.ftz.f32 %0, %1;" : "=f"(r) : "f"(x)); return r;
}
__device__ __forceinline__ float lg2(float x) {
    float r; asm("lg2.approx.ftz.f32 %0, %1;" : "=f"(r) : "f"(x)); return r;
}
__device__ __forceinline__ float frcp(float x) {
    float r; asm("rcp.approx.ftz.f32 %0, %1;" : "=f"(r) : "f"(x)); return r;
}

#define CP_ASYNC16(sa, ga) \
    asm volatile("cp.async.cg.shared.global [%0], [%1], 16;" :: "r"(sa), "l"(ga))
#define CP_COMMIT() asm volatile("cp.async.commit_group;" ::: "memory")

// Core KL for one sample; logits come from SMEM (5 scalar + 2 indexed reads).
__device__ __forceinline__ float kl_sample_smem(float s, const float* __restrict__ l) {
    // Soft target = (1-f) on bin j, f on bin j+1.
    float u = fmaf(s, 5.0f, -0.5f);
    u = fminf(fmaxf(u, 0.0f), 4.0f);
    int j = (int)u;                         // trunc == floor (u >= 0)
    j = min(j, 3);
    float f = u - (float)j;                 // in [0,1]

    float l0 = l[0], l1 = l[1], l2 = l[2], l3 = l[3], l4 = l[4];
    float lj  = l[j];
    float lj1 = l[j + 1];

    float e_b = ex2(f * L2E_T);             // exp(f/T)
    float e_a = ex2(fmaf(-f, L2E_T, L2E_T)); // exp((1-f)/T)
    float Zp  = e_a + e_b + 3.0f;
    float Sps = fmaf(f, e_b - e_a, e_a);    // Zp * sum(p * soft)

    float Zq = ex2(l0 * L2E_T) + ex2(l1 * L2E_T) + ex2(l2 * L2E_T)
             + ex2(l3 * L2E_T) + ex2(l4 * L2E_T);
    float suml = (l0 + l1) + (l2 + l3) + l4;
    float wl = suml + fmaf(e_a - 1.0f, lj, (e_b - 1.0f) * lj1); // Zp * sum(p*l)

    float rZp = frcp(Zp);
    // kl_i = (Sps - wl)/(Zp*T) + log(Zq/Zp)
    return (Sps - wl) * rZp * INV_T + lg2(Zq * rZp) * LN2;
}

__device__ __forceinline__ float sel4(float a0, float a1, float a2, float a3, int i) {
    float r = a0;
    r = (i == 1) ? a1 : r;
    r = (i == 2) ? a2 : r;
    r = (i == 3) ? a3 : r;
    return r;
}

// Register-path variant for the scalar tail.
__device__ __forceinline__ float kl_sample_reg(float s, float l0, float l1,
                                               float l2, float l3, float l4) {
    float u = fmaf(s, 5.0f, -0.5f);
    u = fminf(fmaxf(u, 0.0f), 4.0f);
    int j = (int)u;
    j = min(j, 3);
    float f = u - (float)j;

    float lj  = sel4(l0, l1, l2, l3, j);
    float lj1 = sel4(l1, l2, l3, l4, j);

    float e_b = ex2(f * L2E_T);
    float e_a = ex2(fmaf(-f, L2E_T, L2E_T));
    float Zp  = e_a + e_b + 3.0f;
    float Sps = fmaf(f, e_b - e_a, e_a);

    float Zq = ex2(l0 * L2E_T) + ex2(l1 * L2E_T) + ex2(l2 * L2E_T)
             + ex2(l3 * L2E_T) + ex2(l4 * L2E_T);
    float suml = (l0 + l1) + (l2 + l3) + l4;
    float wl = suml + fmaf(e_a - 1.0f, lj, (e_b - 1.0f) * lj1);

    float rZp = frcp(Zp);
    return (Sps - wl) * rZp * INV_T + lg2(Zq * rZp) * LN2;
}

__global__ void __launch_bounds__(256)
cl_fused_kernel(const float* __restrict__ qs, const float* __restrict__ lg,
                float* __restrict__ out, int n) {
    // Per warp: 2 buffers x 160 float4 (2560B each) = 5120B; 8 warps = 40KB.
    __shared__ float4 sdata4[8 * 320];
    __shared__ float warp_sums[8];
    __shared__ int   s_is_last;

    int lane = threadIdx.x & 31;
    int wid  = threadIdx.x >> 5;
    float4* wslice = sdata4 + wid * 320;
    unsigned int sbase = (unsigned int)__cvta_generic_to_shared(wslice)
                       + (unsigned int)lane * 16u;

    int warp_g = blockIdx.x * 8 + wid;
    int nwarps = gridDim.x * 8;
    int ntiles = n >> 7;                    // 128 samples per warp tile

    const float4* lg4 = (const float4*)lg;

    float acc = 0.0f;

    int t = warp_g;
    if (t < ntiles) {
        // ---- prologue: async-stage first tile into buffer 0 ----
        {
            const float4* g = lg4 + (size_t)t * 160 + lane;
            CP_ASYNC16(sbase,          g);
            CP_ASYNC16(sbase + 512u,   g + 32);
            CP_ASYNC16(sbase + 1024u,  g + 64);
            CP_ASYNC16(sbase + 1536u,  g + 96);
            CP_ASYNC16(sbase + 2048u,  g + 128);
            CP_COMMIT();
        }
        int sb = t << 7;
        float s0 = qs[sb + lane];
        float s1 = qs[sb + lane + 32];
        float s2 = qs[sb + lane + 64];
        float s3 = qs[sb + lane + 96];

        int b = 0;
        for (;;) {
            int tn = t + nwarps;
            bool more = (tn < ntiles);
            float ns0 = 0.f, ns1 = 0.f, ns2 = 0.f, ns3 = 0.f;
            if (more) {
                // stream next tile into the other buffer (overlaps compute below)
                const float4* g = lg4 + (size_t)tn * 160 + lane;
                unsigned int sd = sbase + (unsigned int)(b ^ 1) * 2560u;
                CP_ASYNC16(sd,          g);
                CP_ASYNC16(sd + 512u,   g + 32);
                CP_ASYNC16(sd + 1024u,  g + 64);
                CP_ASYNC16(sd + 1536u,  g + 96);
                CP_ASYNC16(sd + 2048u,  g + 128);
                CP_COMMIT();
                int nsb = tn << 7;
                ns0 = qs[nsb + lane];
                ns1 = qs[nsb + lane + 32];
                ns2 = qs[nsb + lane + 64];
                ns3 = qs[nsb + lane + 96];
            }

            // wait for current buffer's copies (per-lane), then warp-sync so
            // every lane's copies are complete before cross-lane SMEM reads.
            if (more) { asm volatile("cp.async.wait_group 1;" ::: "memory"); }
            else      { asm volatile("cp.async.wait_group 0;" ::: "memory"); }
            __syncwarp();

            // compute current tile: lane i -> samples i, i+32, i+64, i+96;
            // float index 5*sample + c -> bank (5*lane + c) mod 32, conflict-free.
            const float* swf = (const float*)(wslice + b * 160);
            acc += kl_sample_smem(s0, swf + lane * 5);
            acc += kl_sample_smem(s1, swf + (lane + 32) * 5);
            acc += kl_sample_smem(s2, swf + (lane + 64) * 5);
            acc += kl_sample_smem(s3, swf + (lane + 96) * 5);
            __syncwarp();                   // reads done before buffer reuse

            if (!more) break;
            s0 = ns0; s1 = ns1; s2 = ns2; s3 = ns3;
            b ^= 1;
            t = tn;
        }
    }

    // Scalar tail (n % 128 samples), direct global loads.
    int rem_base = ntiles << 7;
    int gid = blockIdx.x * blockDim.x + threadIdx.x;
    if (gid < (n - rem_base)) {
        int i = rem_base + gid;
        const float* l = lg + (size_t)i * NUM_CLASSES;
        acc += kl_sample_reg(qs[i], l[0], l[1], l[2], l[3], l[4]);
    }

    // ---- intra-block reduction ----
    #pragma unroll
    for (int off = 16; off > 0; off >>= 1)
        acc += __shfl_xor_sync(0xFFFFFFFF, acc, off);

    if (lane == 0) warp_sums[wid] = acc;
    __syncthreads();

    if (threadIdx.x == 0) {
        float bs = 0.0f;
        #pragma unroll
        for (int w = 0; w < 8; w++) bs += warp_sums[w];
        g_partials[blockIdx.x] = bs;
        __threadfence();
        unsigned int old = atomicAdd(&g_count, 1u);
        s_is_last = (old == gridDim.x - 1) ? 1 : 0;
    }
    __syncthreads();

    // ---- last block finalizes (deterministic order) ----
    if (s_is_last) {
        __threadfence();
        float fs = 0.0f;
        for (int i = threadIdx.x; i < gridDim.x; i += blockDim.x)
            fs += __ldcg(&g_partials[i]);

        #pragma unroll
        for (int off = 16; off > 0; off >>= 1)
            fs += __shfl_xor_sync(0xFFFFFFFF, fs, off);
        if (lane == 0) warp_sums[wid] = fs;
        __syncthreads();

        if (threadIdx.x == 0) {
            double total = 0.0;
            #pragma unroll
            for (int w = 0; w < 8; w++) total += (double)warp_sums[w];
            out[0] = (float)(total / (double)n * (double)(TEMP * TEMP));
            g_count = 0;    // reset for next graph replay
        }
    }
}

extern "C" void kernel_launch(void* const* d_in, const int* in_sizes, int n_in,
                              void* d_out, int out_size) {
    const float* qs = (const float*)d_in[0];   // quality_score [B]
    const float* lg = (const float*)d_in[1];   // class_logits  [B, 5]
    float* out = (float*)d_out;
    int n = in_sizes[0];

    int blocks = GRID_BLOCKS;
    int ntiles = n >> 7;
    if (ntiles < 1) ntiles = 1;
    if (blocks * 8 > ntiles) blocks = (ntiles + 7) / 8;   // small-n safety
    if (blocks < 1) blocks = 1;
    if (blocks > MAX_BLOCKS) blocks = MAX_BLOCKS;

    cl_fused_kernel<<<blocks, 256>>>(qs, lg, out, n);
}